// round 4
// baseline (speedup 1.0000x reference)
#include <cuda_runtime.h>
#include <cuda_bf16.h>

#define HH 2048
#define WW 2048
#define CC 16
#define TX 32
#define TY 16
#define HTX (TX + 2)   // 34
#define HTY (TY + 2)   // 18
#define HALO_PIX (HTX * HTY)  // 612
#define NTHREADS (TX * TY)    // 512

__device__ __forceinline__ float dot4(float4 a, float4 b) {
    return a.x * b.x + a.y * b.y + a.z * b.z + a.w * b.w;
}

__global__ __launch_bounds__(NTHREADS)
void cos_sim_kernel(const float* __restrict__ img, float* __restrict__ out) {
    __shared__ float rinv[HALO_PIX];

    const int tx = threadIdx.x;
    const int ty = threadIdx.y;
    const int bx = blockIdx.x * TX;
    const int by = blockIdx.y * TY;
    const int tid = ty * TX + tx;

    // ---- Phase 1: inverse norms for the 34x18 halo tile (1 rsqrt per pixel, shared) ----
    #pragma unroll
    for (int it = 0; it < 2; it++) {
        int p = tid + it * NTHREADS;
        if (p < HALO_PIX) {
            int ly = p / HTX;
            int lx = p - ly * HTX;
            int py = by - 1 + ly;
            int px = bx - 1 + lx;
            float r = 0.0f;
            if ((unsigned)py < HH && (unsigned)px < WW) {
                const float4* v = (const float4*)(img + ((size_t)py * WW + px) * CC);
                float4 v0 = v[0], v1 = v[1], v2 = v[2], v3 = v[3];
                float s = dot4(v0, v0) + dot4(v1, v1) + dot4(v2, v2) + dot4(v3, v3);
                r = rsqrtf(fmaxf(s, 1e-24f));
            }
            rinv[p] = r;
        }
    }
    __syncthreads();

    // ---- Phase 2: 4 diagonal cosine similarities ----
    const int gx = bx + tx;
    const int gy = by + ty;

    const float4* a = (const float4*)(img + ((size_t)gy * WW + gx) * CC);
    float4 a0 = a[0], a1 = a[1], a2 = a[2], a3 = a[3];
    const float ra = rinv[(ty + 1) * HTX + (tx + 1)];

    float sim = 0.0f;
    #pragma unroll
    for (int dy = -1; dy <= 1; dy += 2) {
        #pragma unroll
        for (int dx = -1; dx <= 1; dx += 2) {
            int ny = gy + dy;
            int nx = gx + dx;
            if ((unsigned)ny < HH && (unsigned)nx < WW) {
                const float4* b = (const float4*)(img + ((size_t)ny * WW + nx) * CC);
                float4 b0 = b[0], b1 = b[1], b2 = b[2], b3 = b[3];
                float dot = dot4(a0, b0) + dot4(a1, b1) + dot4(a2, b2) + dot4(a3, b3);
                float rb = rinv[(ty + 1 + dy) * HTX + (tx + 1 + dx)];
                sim += dot * (ra * rb);
            }
        }
    }

    out[(size_t)gy * WW + gx] = sim;
}

extern "C" void kernel_launch(void* const* d_in, const int* in_sizes, int n_in,
                              void* d_out, int out_size) {
    const float* img = (const float*)d_in[0];
    float* out = (float*)d_out;

    dim3 block(TX, TY);
    dim3 grid(WW / TX, HH / TY);   // 64 x 128, exact cover
    cos_sim_kernel<<<grid, block>>>(img, out);
}

// round 5
// speedup vs baseline: 1.9078x; 1.9078x over previous
#include <cuda_runtime.h>
#include <cuda_bf16.h>

#define HH 2048
#define WW 2048
#define TX 32
#define TY 16
#define HTX (TX + 2)            // 34
#define HTY (TY + 2)            // 18
#define HALO_PIX (HTX * HTY)    // 612
#define NTHREADS (TX * TY)      // 512
#define N_F4 (HALO_PIX * 4)     // 2448 float4 copies per tile
#define ROW_F4 (HTX * 4)        // 136 float4 per halo row
#define SPITCH 2472             // floats per chunk array: 2448 + 24 pad, 2472 % 32 == 8

__device__ __forceinline__ float dot4(float4 a, float4 b) {
    return a.x * b.x + a.y * b.y + a.z * b.z + a.w * b.w;
}

__global__ __launch_bounds__(NTHREADS)
void cos_sim_kernel(const float* __restrict__ img, float* __restrict__ out) {
    __shared__ float sV[4 * SPITCH];     // SoA: chunk c of pixel p at sV[c*SPITCH + p*4]
    __shared__ float rinv[HALO_PIX];

    const int tx = threadIdx.x;
    const int ty = threadIdx.y;
    const int bx = blockIdx.x * TX;
    const int by = blockIdx.y * TY;
    const int tid = ty * TX + tx;

    const float4* __restrict__ img4 = (const float4*)img;

    // ---- Stage: coalesced global -> SoA smem (zero-padded halo) ----
    #pragma unroll
    for (int it = 0; it < 5; it++) {
        int q = tid + it * NTHREADS;
        if (q < N_F4) {
            int row = q / ROW_F4;
            int c4  = q - row * ROW_F4;
            int px  = c4 >> 2;
            int ch  = c4 & 3;
            int gy  = by - 1 + row;
            int gx  = bx - 1 + px;
            float4 v = make_float4(0.f, 0.f, 0.f, 0.f);
            if ((unsigned)gy < HH && (unsigned)gx < WW)
                v = img4[((size_t)gy * WW + gx) * 4 + ch];
            *(float4*)&sV[ch * SPITCH + (row * HTX + px) * 4] = v;
        }
    }
    __syncthreads();

    // ---- Inverse norms: one rsqrt per halo pixel, shared ----
    #pragma unroll
    for (int it = 0; it < 2; it++) {
        int p = tid + it * NTHREADS;
        if (p < HALO_PIX) {
            float4 v0 = *(float4*)&sV[0 * SPITCH + p * 4];
            float4 v1 = *(float4*)&sV[1 * SPITCH + p * 4];
            float4 v2 = *(float4*)&sV[2 * SPITCH + p * 4];
            float4 v3 = *(float4*)&sV[3 * SPITCH + p * 4];
            float s = dot4(v0, v0) + dot4(v1, v1) + dot4(v2, v2) + dot4(v3, v3);
            rinv[p] = rsqrtf(fmaxf(s, 1e-24f));
        }
    }
    __syncthreads();

    // ---- 4 diagonal cosine similarities (no branches: halo is zero-padded,
    //      so OOB neighbors contribute exactly 0, matching the reference) ----
    const int pc = (ty + 1) * HTX + (tx + 1);
    float4 a0 = *(float4*)&sV[0 * SPITCH + pc * 4];
    float4 a1 = *(float4*)&sV[1 * SPITCH + pc * 4];
    float4 a2 = *(float4*)&sV[2 * SPITCH + pc * 4];
    float4 a3 = *(float4*)&sV[3 * SPITCH + pc * 4];
    const float ra = rinv[pc];

    float sim = 0.0f;
    #pragma unroll
    for (int dy = -1; dy <= 1; dy += 2) {
        #pragma unroll
        for (int dx = -1; dx <= 1; dx += 2) {
            int pn = pc + dy * HTX + dx;
            float4 b0 = *(float4*)&sV[0 * SPITCH + pn * 4];
            float4 b1 = *(float4*)&sV[1 * SPITCH + pn * 4];
            float4 b2 = *(float4*)&sV[2 * SPITCH + pn * 4];
            float4 b3 = *(float4*)&sV[3 * SPITCH + pn * 4];
            float dot = dot4(a0, b0) + dot4(a1, b1) + dot4(a2, b2) + dot4(a3, b3);
            sim += dot * (ra * rinv[pn]);
        }
    }

    out[(size_t)(by + ty) * WW + (bx + tx)] = sim;
}

extern "C" void kernel_launch(void* const* d_in, const int* in_sizes, int n_in,
                              void* d_out, int out_size) {
    const float* img = (const float*)d_in[0];
    float* out = (float*)d_out;

    dim3 block(TX, TY);
    dim3 grid(WW / TX, HH / TY);   // 64 x 128, exact cover
    cos_sim_kernel<<<grid, block>>>(img, out);
}

// round 7
// speedup vs baseline: 2.2576x; 1.1833x over previous
#include <cuda_runtime.h>
#include <cuda_fp16.h>

#define HH 2048
#define WW 2048
#define TX 32
#define TY 16
#define HTX (TX + 2)            // 34
#define HTY (TY + 2)            // 18
#define HALO_PIX (HTX * HTY)    // 612
#define NTHREADS (TX * TY)      // 512
#define N_F4 (HALO_PIX * 4)     // 2448 float4 loads per tile (4 chunks/pixel)
#define ROW_F4 (HTX * 4)        // 136 float4 per halo row
#define HPITCH (HALO_PIX * 16)  // bytes per half-chunk plane (16 B = 8 ch as 4 half2)

__device__ __forceinline__ float dot4(float4 a, float4 b) {
    return a.x * b.x + a.y * b.y + a.z * b.z + a.w * b.w;
}

__global__ __launch_bounds__(NTHREADS)
void cos_sim_kernel(const float* __restrict__ img, float* __restrict__ out) {
    // Two planes of normalized fp16 vectors: plane c2 holds channels [8c2, 8c2+8)
    // of pixel p at byte offset c2*HPITCH + p*16.
    __shared__ __align__(16) unsigned char sH[2 * HPITCH];

    const int tx = threadIdx.x;
    const int ty = threadIdx.y;
    const int bx = blockIdx.x * TX;
    const int by = blockIdx.y * TY;
    const int tid = ty * TX + tx;

    const float4* __restrict__ img4 = (const float4*)img;

    // ---- Stage: coalesced LDG -> shfl-reduced norm -> normalize -> fp16 STS ----
    // q enumerates (row, pixel, chunk); the 4 lanes of a chunk-group share a pixel.
    #pragma unroll
    for (int it = 0; it < 5; it++) {
        int q = tid + it * NTHREADS;
        bool active = q < N_F4;

        int row = q / ROW_F4;
        int rem = q - row * ROW_F4;
        int px  = rem >> 2;
        int ch  = rem & 3;
        int gy  = by - 1 + row;
        int gx  = bx - 1 + px;

        float4 v = make_float4(0.f, 0.f, 0.f, 0.f);
        if (active && (unsigned)gy < HH && (unsigned)gx < WW)
            v = img4[((size_t)gy * WW + gx) * 4 + ch];

        // 4-lane butterfly: all lanes of the group get the full |v|^2.
        float s = dot4(v, v);
        s += __shfl_xor_sync(0xffffffffu, s, 1);
        s += __shfl_xor_sync(0xffffffffu, s, 2);
        float r = rsqrtf(fmaxf(s, 1e-24f));   // zero halo -> 0 * big = 0

        if (active) {
            half2 ha = __floats2half2_rn(v.x * r, v.y * r);
            half2 hb = __floats2half2_rn(v.z * r, v.w * r);
            unsigned off = (unsigned)(ch >> 1) * HPITCH
                         + (unsigned)(row * HTX + px) * 16u
                         + (unsigned)(ch & 1) * 8u;
            uint2 pkt = make_uint2(*(const unsigned*)&ha, *(const unsigned*)&hb);
            *(uint2*)(sH + off) = pkt;
        }
    }
    __syncthreads();

    // ---- Phase 2: 4 diagonal cosines, vectors already unit-length fp16 ----
    const int pc = (ty + 1) * HTX + (tx + 1);

    float2 cf[8];
    {
        uint4 u0 = *(const uint4*)(sH + 0 * HPITCH + pc * 16);
        uint4 u1 = *(const uint4*)(sH + 1 * HPITCH + pc * 16);
        const half2* h0 = (const half2*)&u0;
        const half2* h1 = (const half2*)&u1;
        #pragma unroll
        for (int j = 0; j < 4; j++) {
            cf[j]     = __half22float2(h0[j]);
            cf[4 + j] = __half22float2(h1[j]);
        }
    }

    float sim = 0.0f;
    #pragma unroll
    for (int dy = -1; dy <= 1; dy += 2) {
        #pragma unroll
        for (int dx = -1; dx <= 1; dx += 2) {
            int pn = pc + dy * HTX + dx;
            uint4 u0 = *(const uint4*)(sH + 0 * HPITCH + pn * 16);
            uint4 u1 = *(const uint4*)(sH + 1 * HPITCH + pn * 16);
            const half2* h0 = (const half2*)&u0;
            const half2* h1 = (const half2*)&u1;
            float d = 0.0f;
            #pragma unroll
            for (int j = 0; j < 4; j++) {
                float2 f0 = __half22float2(h0[j]);
                float2 f1 = __half22float2(h1[j]);
                d = fmaf(cf[j].x,     f0.x, d);
                d = fmaf(cf[j].y,     f0.y, d);
                d = fmaf(cf[4 + j].x, f1.x, d);
                d = fmaf(cf[4 + j].y, f1.y, d);
            }
            sim += d;
        }
    }

    out[(size_t)(by + ty) * WW + (bx + tx)] = sim;
}

extern "C" void kernel_launch(void* const* d_in, const int* in_sizes, int n_in,
                              void* d_out, int out_size) {
    const float* img = (const float*)d_in[0];
    float* out = (float*)d_out;

    dim3 block(TX, TY);
    dim3 grid(WW / TX, HH / TY);   // 64 x 128, exact cover
    cos_sim_kernel<<<grid, block>>>(img, out);
}

// round 8
// speedup vs baseline: 2.6291x; 1.1646x over previous
#include <cuda_runtime.h>
#include <cuda_fp16.h>

#define HH 2048
#define WW 2048
#define TX 32
#define TY 16
#define HTX (TX + 2)            // 34
#define HTY (TY + 2)            // 18
#define HALO_PIX (HTX * HTY)    // 612
#define NTHREADS (TX * TY)      // 512
#define N_F4 (HALO_PIX * 4)     // 2448 float4 loads per tile
#define ROW_F4 (HTX * 4)        // 136 float4 per halo row
#define HPITCH (HALO_PIX * 16)  // bytes per fp16 plane (16 B per pixel per plane)
#define DOT_ROWS (TY + 1)       // 17
#define DOT_POS (DOT_ROWS * HTX) // 578 dot-grid positions

__device__ __forceinline__ float dot4(float4 a, float4 b) {
    return a.x * b.x + a.y * b.y + a.z * b.z + a.w * b.w;
}

// Accumulate f32 dot contribution of one 8-channel plane packet pair.
__device__ __forceinline__ float dot_u4(uint4 a, uint4 b, float acc) {
    const half2* ha = (const half2*)&a;
    const half2* hb = (const half2*)&b;
    #pragma unroll
    for (int j = 0; j < 4; j++) {
        float2 fa = __half22float2(ha[j]);
        float2 fb = __half22float2(hb[j]);
        acc = fmaf(fa.x, fb.x, acc);
        acc = fmaf(fa.y, fb.y, acc);
    }
    return acc;
}

__global__ __launch_bounds__(NTHREADS, 3)
void cos_sim_kernel(const float* __restrict__ img, float* __restrict__ out) {
    // Normalized fp16 vectors, 2 planes of 8 channels: plane c2, pixel p at
    // byte offset c2*HPITCH + p*16.
    __shared__ __align__(16) unsigned char sH[2 * HPITCH];
    __shared__ float sD1[DOT_POS];   // dot(p, p + (1,+1))
    __shared__ float sD2[DOT_POS];   // dot(p, p + (1,-1))

    const int tx = threadIdx.x;
    const int ty = threadIdx.y;
    const int bx = blockIdx.x * TX;
    const int by = blockIdx.y * TY;
    const int tid = ty * TX + tx;

    const float4* __restrict__ img4 = (const float4*)img;

    // ---- Stage: coalesced LDG -> shfl norm -> normalize -> fp16 STS ----
    #pragma unroll
    for (int it = 0; it < 5; it++) {
        int q = tid + it * NTHREADS;
        bool active = q < N_F4;

        int row = q / ROW_F4;
        int rem = q - row * ROW_F4;
        int px  = rem >> 2;
        int ch  = rem & 3;
        int gy  = by - 1 + row;
        int gx  = bx - 1 + px;

        float4 v = make_float4(0.f, 0.f, 0.f, 0.f);
        if (active && (unsigned)gy < HH && (unsigned)gx < WW)
            v = img4[((size_t)gy * WW + gx) * 4 + ch];

        float s = dot4(v, v);
        s += __shfl_xor_sync(0xffffffffu, s, 1);
        s += __shfl_xor_sync(0xffffffffu, s, 2);
        float r = rsqrtf(fmaxf(s, 1e-24f));    // zero halo stays exactly zero

        if (active) {
            half2 ha = __floats2half2_rn(v.x * r, v.y * r);
            half2 hb = __floats2half2_rn(v.z * r, v.w * r);
            unsigned off = (unsigned)(ch >> 1) * HPITCH
                         + (unsigned)(row * HTX + px) * 16u
                         + (unsigned)(ch & 1) * 8u;
            *(uint2*)(sH + off) = make_uint2(*(const unsigned*)&ha,
                                             *(const unsigned*)&hb);
        }
    }
    __syncthreads();

    // ---- Dot pass: each diagonal pair dot computed ONCE ----
    // Position p=(row,col), row 0..16: D1[p]=dot(p, p+HTX+1), D2[p]=dot(p, p+HTX-1).
    #pragma unroll
    for (int it = 0; it < 2; it++) {
        int p = tid + it * NTHREADS;
        if (p < DOT_POS) {
            int row = p / HTX;
            int col = p - row * HTX;
            bool do1 = (col <= HTX - 2);   // pair partner col+1 in range
            bool do2 = (col >= 1);         // pair partner col-1 in range
            int pdr = p + HTX + 1;
            int pdl = p + HTX - 1;

            float d1 = 0.0f, d2 = 0.0f;
            #pragma unroll
            for (int pl = 0; pl < 2; pl++) {
                uint4 ub = *(const uint4*)(sH + pl * HPITCH + p * 16);
                if (do1) {
                    uint4 ur = *(const uint4*)(sH + pl * HPITCH + pdr * 16);
                    d1 = dot_u4(ub, ur, d1);
                }
                if (do2) {
                    uint4 ul = *(const uint4*)(sH + pl * HPITCH + pdl * 16);
                    d2 = dot_u4(ub, ul, d2);
                }
            }
            if (do1) sD1[p] = d1;
            if (do2) sD2[p] = d2;
        }
    }
    __syncthreads();

    // ---- Gather: each output sums its 4 shared pair-dots ----
    const int pc = (ty + 1) * HTX + (tx + 1);
    float sim = (sD1[pc] + sD1[pc - HTX - 1])     // (+1,+1) and (-1,-1)
              + (sD2[pc] + sD2[pc - HTX + 1]);    // (+1,-1) and (-1,+1)

    out[(size_t)(by + ty) * WW + (bx + tx)] = sim;
}

extern "C" void kernel_launch(void* const* d_in, const int* in_sizes, int n_in,
                              void* d_out, int out_size) {
    const float* img = (const float*)d_in[0];
    float* out = (float*)d_out;

    dim3 block(TX, TY);
    dim3 grid(WW / TX, HH / TY);   // 64 x 128, exact cover
    cos_sim_kernel<<<grid, block>>>(img, out);
}

// round 9
// speedup vs baseline: 2.8336x; 1.0778x over previous
#include <cuda_runtime.h>
#include <cuda_fp16.h>

#define HH 2048
#define WW 2048
#define TX 32
#define TY 16
#define HTX (TX + 2)            // 34
#define HTY (TY + 2)            // 18
#define HALO_PIX (HTX * HTY)    // 612
#define NTHREADS (TX * TY)      // 512
#define N_F4 (HALO_PIX * 4)     // 2448 float4 loads per tile
#define ROW_F4 (HTX * 4)        // 136 float4 per halo row
#define HPITCH (HALO_PIX * 16)  // bytes per fp16 plane (16 B per pixel per plane)
#define DOT_ROWS (TY + 1)       // 17
#define DOT_POS (DOT_ROWS * HTX) // 578 dot-grid positions

__device__ __forceinline__ float dot4(float4 a, float4 b) {
    return a.x * b.x + a.y * b.y + a.z * b.z + a.w * b.w;
}

// 8-channel packet dot, fp16 multiply/accumulate (4-deep chain), one f32
// reduction at the end. Error per packet ~1e-4 abs — well inside budget.
__device__ __forceinline__ float dot_pkt(uint4 a, uint4 b) {
    const half2* ha = (const half2*)&a;
    const half2* hb = (const half2*)&b;
    half2 acc = __hmul2(ha[0], hb[0]);
    acc = __hfma2(ha[1], hb[1], acc);
    acc = __hfma2(ha[2], hb[2], acc);
    acc = __hfma2(ha[3], hb[3], acc);
    float2 f = __half22float2(acc);
    return f.x + f.y;
}

__global__ __launch_bounds__(NTHREADS, 3)
void cos_sim_kernel(const float* __restrict__ img, float* __restrict__ out) {
    // Normalized fp16 vectors, 2 planes of 8 channels: plane c2, pixel p at
    // byte offset c2*HPITCH + p*16.
    __shared__ __align__(16) unsigned char sH[2 * HPITCH];
    __shared__ float sD1[DOT_POS];   // dot(p, p + (1,+1))
    __shared__ float sD2[DOT_POS];   // dot(p, p + (1,-1))

    const int tx = threadIdx.x;
    const int ty = threadIdx.y;
    const int bx = blockIdx.x * TX;
    const int by = blockIdx.y * TY;
    const int tid = ty * TX + tx;

    const float4* __restrict__ img4 = (const float4*)img;

    // ---- Stage: coalesced LDG -> shfl norm -> normalize -> fp16 STS ----
    #pragma unroll
    for (int it = 0; it < 5; it++) {
        int q = tid + it * NTHREADS;
        bool active = q < N_F4;

        int row = q / ROW_F4;
        int rem = q - row * ROW_F4;
        int px  = rem >> 2;
        int ch  = rem & 3;
        int gy  = by - 1 + row;
        int gx  = bx - 1 + px;

        float4 v = make_float4(0.f, 0.f, 0.f, 0.f);
        if (active && (unsigned)gy < HH && (unsigned)gx < WW)
            v = img4[((size_t)gy * WW + gx) * 4 + ch];

        float s = dot4(v, v);
        s += __shfl_xor_sync(0xffffffffu, s, 1);
        s += __shfl_xor_sync(0xffffffffu, s, 2);
        float r = rsqrtf(fmaxf(s, 1e-24f));    // zero halo stays exactly zero

        if (active) {
            half2 ha = __floats2half2_rn(v.x * r, v.y * r);
            half2 hb = __floats2half2_rn(v.z * r, v.w * r);
            unsigned off = (unsigned)(ch >> 1) * HPITCH
                         + (unsigned)(row * HTX + px) * 16u
                         + (unsigned)(ch & 1) * 8u;
            *(uint2*)(sH + off) = make_uint2(*(const unsigned*)&ha,
                                             *(const unsigned*)&hb);
        }
    }
    __syncthreads();

    // ---- Dot pass: each diagonal pair dot computed ONCE, fp16 math ----
    #pragma unroll
    for (int it = 0; it < 2; it++) {
        int p = tid + it * NTHREADS;
        if (p < DOT_POS) {
            int row = p / HTX;
            int col = p - row * HTX;
            bool do1 = (col <= HTX - 2);   // partner col+1 in range
            bool do2 = (col >= 1);         // partner col-1 in range
            int pdr = p + HTX + 1;
            int pdl = p + HTX - 1;

            float d1 = 0.0f, d2 = 0.0f;
            #pragma unroll
            for (int pl = 0; pl < 2; pl++) {
                uint4 ub = *(const uint4*)(sH + pl * HPITCH + p * 16);
                if (do1) {
                    uint4 ur = *(const uint4*)(sH + pl * HPITCH + pdr * 16);
                    d1 += dot_pkt(ub, ur);
                }
                if (do2) {
                    uint4 ul = *(const uint4*)(sH + pl * HPITCH + pdl * 16);
                    d2 += dot_pkt(ub, ul);
                }
            }
            if (do1) sD1[p] = d1;
            if (do2) sD2[p] = d2;
        }
    }
    __syncthreads();

    // ---- Gather: each output sums its 4 shared pair-dots ----
    const int pc = (ty + 1) * HTX + (tx + 1);
    float sim = (sD1[pc] + sD1[pc - HTX - 1])     // (+1,+1) and (-1,-1)
              + (sD2[pc] + sD2[pc - HTX + 1]);    // (+1,-1) and (-1,+1)

    out[(size_t)(by + ty) * WW + (bx + tx)] = sim;
}

extern "C" void kernel_launch(void* const* d_in, const int* in_sizes, int n_in,
                              void* d_out, int out_size) {
    const float* img = (const float*)d_in[0];
    float* out = (float*)d_out;

    dim3 block(TX, TY);
    dim3 grid(WW / TX, HH / TY);   // 64 x 128, exact cover
    cos_sim_kernel<<<grid, block>>>(img, out);
}

// round 10
// speedup vs baseline: 3.1155x; 1.0995x over previous
#include <cuda_runtime.h>
#include <cuda_fp16.h>

#define HH 2048
#define WW 2048
#define TX 32
#define TYO 32                   // output rows per block (2 per thread)
#define NTHREADS 512
#define HTX 34
#define HTY 34
#define HALO_PIX (HTX * HTY)     // 1156
#define HPITCH (HALO_PIX * 16)   // bytes per fp16 plane
#define BODY_F4 (HTY * 32 * 4)   // 4352 float4 in the div-free body region
#define DOT_ROWS (TYO + 1)       // 33
#define DOT_POS (DOT_ROWS * HTX) // 1122

__device__ __forceinline__ float dot4(float4 a, float4 b) {
    return a.x * b.x + a.y * b.y + a.z * b.z + a.w * b.w;
}

__device__ __forceinline__ unsigned h2u(half2 h) {
    return *(const unsigned*)&h;
}

// 8-channel packet dot: fp16 mul/acc (4-deep), f32 finish.
__device__ __forceinline__ float dot_pkt(uint4 a, uint4 b) {
    const half2* ha = (const half2*)&a;
    const half2* hb = (const half2*)&b;
    half2 acc = __hmul2(ha[0], hb[0]);
    acc = __hfma2(ha[1], hb[1], acc);
    acc = __hfma2(ha[2], hb[2], acc);
    acc = __hfma2(ha[3], hb[3], acc);
    float2 f = __half22float2(acc);
    return f.x + f.y;
}

// Normalize 1 float4 chunk (4 lanes/pixel share the norm) and store as fp16.
__device__ __forceinline__ void norm_store(unsigned char* sH, float4 v,
                                           int pix, int ch, bool write) {
    float s = dot4(v, v);
    s += __shfl_xor_sync(0xffffffffu, s, 1);
    s += __shfl_xor_sync(0xffffffffu, s, 2);
    float r = rsqrtf(fmaxf(s, 1e-24f));
    if (write) {
        half2 ha = __floats2half2_rn(v.x * r, v.y * r);
        half2 hb = __floats2half2_rn(v.z * r, v.w * r);
        unsigned off = (unsigned)(ch >> 1) * HPITCH
                     + (unsigned)pix * 16u + (unsigned)(ch & 1) * 8u;
        *(uint2*)(sH + off) = make_uint2(h2u(ha), h2u(hb));
    }
}

__global__ __launch_bounds__(NTHREADS, 3)
void cos_sim_kernel(const float* __restrict__ img, float* __restrict__ out) {
    __shared__ __align__(16) unsigned char sH[2 * HPITCH];
    __shared__ float sD1[DOT_POS];   // dot(p, p + (1,+1))
    __shared__ float sD2[DOT_POS];   // dot(p, p + (1,-1))

    const int tx = threadIdx.x;
    const int ty = threadIdx.y;      // 0..15
    const int bx = blockIdx.x * TX;
    const int by = blockIdx.y * TYO;
    const int tid = ty * TX + tx;

    const float4* __restrict__ img4 = (const float4*)img;

    // ---- Stage body: halo rows 0..33, cols 1..32. Pure shift indexing. ----
    // q -> (row = q>>7, col = (q>>2)&31, ch = q&3); gx always in-bounds.
    #pragma unroll
    for (int it = 0; it < 9; it++) {
        int q = tid + it * NTHREADS;
        bool active = (it < 8) | (tid < BODY_F4 - 8 * NTHREADS);
        int row = q >> 7;
        int col = (q >> 2) & 31;
        int ch  = q & 3;
        int gy  = by - 1 + row;
        int gx  = bx + col;

        float4 v = make_float4(0.f, 0.f, 0.f, 0.f);
        if (active && (unsigned)gy < HH)
            v = img4[((size_t)gy * WW + gx) * 4 + ch];

        norm_store(sH, v, row * HTX + (col + 1), ch, active);
    }

    // ---- Stage edges: halo cols 0 and 33, all 34 rows (shift-only). ----
    {
        int side = tid >> 8;                 // 0 -> col 0, 1 -> col 33
        int row  = (tid >> 2) & 63;          // active only when < 34
        int ch   = tid & 3;
        bool active = row < HTY;
        int gy = by - 1 + row;
        int gx = bx - 1 + side * 33;         // bx-1 or bx+32

        float4 v = make_float4(0.f, 0.f, 0.f, 0.f);
        if (active && (unsigned)gy < HH && (unsigned)gx < WW)
            v = img4[((size_t)gy * WW + gx) * 4 + ch];

        norm_store(sH, v, row * HTX + side * 33, ch, active);
    }
    __syncthreads();

    // ---- Dot pass: each diagonal pair dot computed ONCE (fp16 math). ----
    #pragma unroll
    for (int it = 0; it < 3; it++) {
        int p = tid + it * NTHREADS;
        if (p < DOT_POS) {
            int row = p / HTX;
            int col = p - row * HTX;
            bool do1 = (col <= HTX - 2);
            bool do2 = (col >= 1);
            int pdr = p + HTX + 1;
            int pdl = p + HTX - 1;

            float d1 = 0.0f, d2 = 0.0f;
            #pragma unroll
            for (int pl = 0; pl < 2; pl++) {
                uint4 ub = *(const uint4*)(sH + pl * HPITCH + p * 16);
                if (do1) {
                    uint4 ur = *(const uint4*)(sH + pl * HPITCH + pdr * 16);
                    d1 += dot_pkt(ub, ur);
                }
                if (do2) {
                    uint4 ul = *(const uint4*)(sH + pl * HPITCH + pdl * 16);
                    d2 += dot_pkt(ub, ul);
                }
            }
            if (do1) sD1[p] = d1;
            if (do2) sD2[p] = d2;
        }
    }
    __syncthreads();

    // ---- Gather: 2 outputs per thread, 4 shared pair-dots each. ----
    #pragma unroll
    for (int half = 0; half < 2; half++) {
        int oy = ty + half * 16;
        int pc = (oy + 1) * HTX + (tx + 1);
        float sim = (sD1[pc] + sD1[pc - HTX - 1])
                  + (sD2[pc] + sD2[pc - HTX + 1]);
        out[(size_t)(by + oy) * WW + (bx + tx)] = sim;
    }
}

extern "C" void kernel_launch(void* const* d_in, const int* in_sizes, int n_in,
                              void* d_out, int out_size) {
    const float* img = (const float*)d_in[0];
    float* out = (float*)d_out;

    dim3 block(TX, 16);
    dim3 grid(WW / TX, HH / TYO);   // 64 x 64
    cos_sim_kernel<<<grid, block>>>(img, out);
}

// round 12
// speedup vs baseline: 3.2069x; 1.0293x over previous
#include <cuda_runtime.h>
#include <cuda_fp16.h>

#define HH 2048
#define WW 2048
#define TX 32
#define TYO 32                    // output rows per block (2 per thread)
#define NTHREADS 512
#define HTX 34
#define HTY 34
#define HALO_PIX (HTX * HTY)      // 1156
#define HPITCH ((HALO_PIX + 1) * 16)  // +1 pad pixel: dot pass reads up to pixel 1156
#define DOT_ROWS (TYO + 1)        // 33
#define DOT_POS (DOT_ROWS * HTX)  // 1122

__device__ __forceinline__ float dot4(float4 a, float4 b) {
    return a.x * b.x + a.y * b.y + a.z * b.z + a.w * b.w;
}

__device__ __forceinline__ unsigned h2u(half2 h) {
    return *(const unsigned*)&h;
}

// 8-channel packet dot: fp16 mul/acc (4-deep chain), f32 finish.
__device__ __forceinline__ float dot_pkt(uint4 a, uint4 b) {
    const half2* ha = (const half2*)&a;
    const half2* hb = (const half2*)&b;
    half2 acc = __hmul2(ha[0], hb[0]);
    acc = __hfma2(ha[1], hb[1], acc);
    acc = __hfma2(ha[2], hb[2], acc);
    acc = __hfma2(ha[3], hb[3], acc);
    float2 f = __half22float2(acc);
    return f.x + f.y;
}

// Normalize one float4 chunk (4 lanes of a pixel share the norm via shfl),
// store as fp16 at precomputed byte offset. All 32 lanes must participate.
__device__ __forceinline__ void norm_store(unsigned char* sH, float4 v,
                                           unsigned off, bool write) {
    float s = dot4(v, v);
    s += __shfl_xor_sync(0xffffffffu, s, 1);
    s += __shfl_xor_sync(0xffffffffu, s, 2);
    float r = rsqrtf(fmaxf(s, 1e-24f));
    if (write) {
        half2 ha = __floats2half2_rn(v.x * r, v.y * r);
        half2 hb = __floats2half2_rn(v.z * r, v.w * r);
        *(uint2*)(sH + off) = make_uint2(h2u(ha), h2u(hb));
    }
}

__global__ __launch_bounds__(NTHREADS, 3)
void cos_sim_kernel(const float* __restrict__ img, float* __restrict__ out) {
    __shared__ __align__(16) unsigned char sH[2 * HPITCH];
    __shared__ float sD1[DOT_POS];   // dot(p, p + (1,+1))
    __shared__ float sD2[DOT_POS];   // dot(p, p + (1,-1))

    const int tx = threadIdx.x;
    const int ty = threadIdx.y;      // 0..15
    const int bx = blockIdx.x * TX;
    const int by = blockIdx.y * TYO;
    const int tid = ty * TX + tx;

    const float4* __restrict__ img4 = (const float4*)img;

    // ---- Stage body: halo rows 0..33, cols 1..32 (pixel cols bx..bx+31). ----
    // Per-thread role fixed: ch = tid&3, col = (tid>>2)&31, row0 = tid>>7 (0..3).
    // Each iteration advances row by 4 -> constant address deltas:
    //   4 rows * WW pixels * 4 float4/pixel = 16*WW float4 elements.
    {
        const int ch   = tid & 3;
        const int col  = (tid >> 2) & 31;
        const int row0 = tid >> 7;
        const int gy0  = by - 1 + row0;
        const float4* gp = img4 + ((long long)gy0 * WW + (bx + col)) * 4 + ch;
        const unsigned soff0 = (unsigned)(ch >> 1) * HPITCH
                             + (unsigned)(row0 * HTX + col + 1) * 16u
                             + (unsigned)(ch & 1) * 8u;

        #pragma unroll
        for (int it = 0; it < 9; it++) {
            bool act = (it < 8) | (tid < 256);       // 4352 f4 = 8.5 * 512
            int gy = gy0 + 4 * it;
            float4 v = make_float4(0.f, 0.f, 0.f, 0.f);
            if (act && (unsigned)gy < HH)
                v = gp[(size_t)it * 16 * WW];        // 4 halo rows per step
            norm_store(sH, v, soff0 + (unsigned)it * (4 * HTX * 16), act);
        }
    }

    // ---- Stage edges: halo cols 0 and 33, rows 0..33. ----
    {
        int side = tid >> 8;                 // 0 -> col 0, 1 -> col 33
        int row  = (tid >> 2) & 63;
        int ch   = tid & 3;
        bool act = row < HTY;
        int gy = by - 1 + row;
        int gx = bx - 1 + side * 33;
        float4 v = make_float4(0.f, 0.f, 0.f, 0.f);
        if (act && (unsigned)gy < HH && (unsigned)gx < WW)
            v = img4[((long long)gy * WW + gx) * 4 + ch];
        unsigned off = (unsigned)(ch >> 1) * HPITCH
                     + (unsigned)(row * HTX + side * 33) * 16u
                     + (unsigned)(ch & 1) * 8u;
        norm_store(sH, v, off, act);
    }
    __syncthreads();

    // ---- Dot pass: each diagonal pair dot ONCE; no edge predicates. ----
    // Edge positions (col 33 for D1, col 0 for D2) compute garbage that the
    // gather never reads; sH pad pixel keeps reads in bounds.
    #pragma unroll
    for (int it = 0; it < 3; it++) {
        int p = tid + it * NTHREADS;
        if (p < DOT_POS) {
            const unsigned a = (unsigned)p * 16u;
            uint4 ub0 = *(const uint4*)(sH + a);
            uint4 ur0 = *(const uint4*)(sH + a + (HTX + 1) * 16);
            uint4 ul0 = *(const uint4*)(sH + a + (HTX - 1) * 16);
            uint4 ub1 = *(const uint4*)(sH + HPITCH + a);
            uint4 ur1 = *(const uint4*)(sH + HPITCH + a + (HTX + 1) * 16);
            uint4 ul1 = *(const uint4*)(sH + HPITCH + a + (HTX - 1) * 16);
            sD1[p] = dot_pkt(ub0, ur0) + dot_pkt(ub1, ur1);
            sD2[p] = dot_pkt(ub0, ul0) + dot_pkt(ub1, ul1);
        }
    }
    __syncthreads();

    // ---- Gather: 2 outputs per thread, 4 shared pair-dots each. ----
    #pragma unroll
    for (int half = 0; half < 2; half++) {
        int oy = ty + half * 16;
        int pc = (oy + 1) * HTX + (tx + 1);
        float sim = (sD1[pc] + sD1[pc - HTX - 1])
                  + (sD2[pc] + sD2[pc - HTX + 1]);
        out[(size_t)(by + oy) * WW + (bx + tx)] = sim;
    }
}

extern "C" void kernel_launch(void* const* d_in, const int* in_sizes, int n_in,
                              void* d_out, int out_size) {
    const float* img = (const float*)d_in[0];
    float* out = (float*)d_out;

    dim3 block(TX, 16);
    dim3 grid(WW / TX, HH / TYO);   // 64 x 64
    cos_sim_kernel<<<grid, block>>>(img, out);
}